// round 17
// baseline (speedup 1.0000x reference)
#include <cuda_runtime.h>
#include <cuda_fp16.h>
#include <math.h>
#include <stdint.h>

// Problem constants
#define BATCH   4
#define SEQ     2048
#define DM      1024
#define NH      16
#define DK      64
#define CHUNKS  32
#define KVLEN   256
#define LNROWS  1985

// ================= PTX helpers (sm_80+ features only) =======================
__device__ __forceinline__ uint32_t smem_u32(const void* p) {
    uint32_t a;
    asm("{ .reg .u64 t; cvta.to.shared.u64 t, %1; cvt.u32.u64 %0, t; }"
        : "=r"(a) : "l"(p));
    return a;
}
#define CP_ASYNC16(smem, gmem) \
    asm volatile("cp.async.cg.shared.global [%0], [%1], 16;" \
                 :: "r"(smem), "l"(gmem))
#define CP_COMMIT() asm volatile("cp.async.commit_group;" ::: "memory")
#define CP_WAIT1()  asm volatile("cp.async.wait_group 1;" ::: "memory")
#define CP_WAIT0()  asm volatile("cp.async.wait_group 0;" ::: "memory")

#define LDSM_X4(r0, r1, r2, r3, addr) \
    asm volatile("ldmatrix.sync.aligned.m8n8.x4.shared.b16 {%0,%1,%2,%3}, [%4];" \
                 : "=r"(r0), "=r"(r1), "=r"(r2), "=r"(r3) : "r"(addr))

#define MMA_F16(d, a, b) \
    asm volatile("mma.sync.aligned.m16n8k16.row.col.f32.f16.f16.f32 " \
                 "{%0,%1,%2,%3}, {%4,%5,%6,%7}, {%8,%9}, {%0,%1,%2,%3};" \
                 : "+f"((d)[0]), "+f"((d)[1]), "+f"((d)[2]), "+f"((d)[3]) \
                 : "r"((a)[0]), "r"((a)[1]), "r"((a)[2]), "r"((a)[3]), \
                   "r"((b)[0]), "r"((b)[1]))

// ================= scratch (device globals) =================================
__device__ __half g_hn16[(size_t)8192 * 1024];
__device__ __half g_e16 [(size_t)32768 * 1024];
__device__ __half g_ao16[(size_t)8192 * 1024];
__device__ __half g_q16 [(size_t)8192 * 1024];
__device__ __half g_k16 [(size_t)32768 * 1024];
__device__ __half g_v16 [(size_t)32768 * 1024];
__device__ __half g_wq16[1024 * 1024];
__device__ __half g_wk16[1024 * 1024];
__device__ __half g_wv16[1024 * 1024];
__device__ __half g_wo16[1024 * 1024];

// ================= prep_all: LN | e->fp16 | 4x cvtT | headcopy ==============
__global__ __launch_bounds__(256) void prep_all(
    const float* __restrict__ h, const float* __restrict__ gamma,
    const float* __restrict__ beta, const float* __restrict__ e,
    const float* __restrict__ Wk, const float* __restrict__ Wq,
    const float* __restrict__ Wv, const float* __restrict__ Wo,
    __half* __restrict__ hn, __half* __restrict__ e16,
    __half* __restrict__ wk16, __half* __restrict__ wq16,
    __half* __restrict__ wv16, __half* __restrict__ wo16,
    float* __restrict__ out) {
    int tid = threadIdx.x;
    int blk = blockIdx.x;

    if (blk >= 45056) {
        int r = blk - 45056;
        int b = r / 63, t = r - b * 63;
        size_t off = ((size_t)b * SEQ + t) * DM + tid * 4;
        *(float4*)&out[off] = *(const float4*)&h[off];
        return;
    }
    if (blk >= 40960) {
        int r = blk - 40960;
        int z = r >> 10;
        int rem = r & 1023;
        int bx = rem & 31, by = rem >> 5;
        const float* W = (z == 0) ? Wk : (z == 1) ? Wq : (z == 2) ? Wv : Wo;
        __half* T      = (z == 0) ? wk16 : (z == 1) ? wq16 : (z == 2) ? wv16 : wo16;
        __shared__ float t[32][33];
        int n0 = bx * 32, k0 = by * 32;
        int tx = tid & 31, ty = tid >> 5;
        for (int rr = ty; rr < 32; rr += 8)
            t[rr][tx] = W[(size_t)(k0 + rr) * 1024 + n0 + tx];
        __syncthreads();
        for (int rr = ty; rr < 32; rr += 8)
            T[(size_t)(n0 + rr) * 1024 + k0 + tx] = __float2half_rn(t[tx][rr]);
        return;
    }
    if (blk >= 8192) {
        size_t i = ((size_t)(blk - 8192) * 1024) + tid * 4;
        float4 v = *(const float4*)&e[i];
        __half o[4] = {__float2half_rn(v.x), __float2half_rn(v.y),
                       __float2half_rn(v.z), __float2half_rn(v.w)};
        *(uint2*)&e16[i] = *(uint2*)o;
        return;
    }
    int row = blk;
    int b = row >> 11;
    int i = row & 2047;
    __half* dst = hn + (size_t)row * DM + tid * 4;
    if (i >= LNROWS) {
        *(uint2*)dst = make_uint2(0u, 0u);
        return;
    }
    const float* src = h + ((size_t)b * SEQ + i + 63) * DM;
    float4 x = *(const float4*)&src[tid * 4];
    float s  = x.x + x.y + x.z + x.w;
    float ss = x.x * x.x + x.y * x.y + x.z * x.z + x.w * x.w;
    #pragma unroll
    for (int o = 16; o; o >>= 1) {
        s  += __shfl_xor_sync(0xffffffffu, s,  o);
        ss += __shfl_xor_sync(0xffffffffu, ss, o);
    }
    __shared__ float rs[8], rss[8];
    int wid = tid >> 5, lane = tid & 31;
    if (lane == 0) { rs[wid] = s; rss[wid] = ss; }
    __syncthreads();
    __shared__ float smu, srstd;
    if (tid == 0) {
        float S = 0.f, SS = 0.f;
        #pragma unroll
        for (int w = 0; w < 8; w++) { S += rs[w]; SS += rss[w]; }
        float mu  = S * (1.0f / DM);
        float var = SS * (1.0f / DM) - mu * mu;
        smu = mu; srstd = rsqrtf(var + 1e-5f);
    }
    __syncthreads();
    float mu = smu, rstd = srstd;
    float4 g = *(const float4*)&gamma[tid * 4];
    float4 be = *(const float4*)&beta[tid * 4];
    __half y[4];
    y[0] = __float2half_rn((x.x - mu) * rstd * g.x + be.x);
    y[1] = __float2half_rn((x.y - mu) * rstd * g.y + be.y);
    y[2] = __float2half_rn((x.z - mu) * rstd * g.z + be.z);
    y[3] = __float2half_rn((x.w - mu) * rstd * g.w + be.w);
    *(uint2*)dst = *(uint2*)y;
}

// ================= GEMM core: 3-stage pipeline, 2 CTAs/SM ===================
// 128x128 CTA tile, 256 threads (2Mx4N warps, 64x32 warp tile),
// K-chunk 64, 3-stage cp.async pipeline (2-chunk lookahead), 110.6KB smem.
#define ROWB   144
#define O_B    18432
#define STG2   36864
#define GSMEM  (3 * STG2)            // 110592

struct GemmFrag {
    float acc[4][4][4];
};

__device__ __forceinline__ void gemm_core(
    const __half* __restrict__ Asrc, const __half* __restrict__ Bsrc,
    char* smc, uint32_t smb, int tid, GemmFrag& f) {
    int wid = tid >> 5, lane = tid & 31;
    int wm = wid & 1, wn = wid >> 1;

    int lr[4], ls[4];
    #pragma unroll
    for (int i = 0; i < 4; i++) {
        int v = tid + i * 256;
        lr[i] = v >> 3;
        ls[i] = v & 7;
    }
    int a_row  = lane & 15;
    int a_kofs = (lane >> 4) * 16;
    int b_rofs = ((lane >> 4) & 1) * 8 + (lane & 7);
    int b_kofs = ((lane >> 3) & 1) * 16;

    #pragma unroll
    for (int mt = 0; mt < 4; mt++)
        #pragma unroll
        for (int nt = 0; nt < 4; nt++)
            #pragma unroll
            for (int i = 0; i < 4; i++) f.acc[mt][nt][i] = 0.f;

    // prologue: chunks 0,1 -> stages 0,1
    #pragma unroll
    for (int pc = 0; pc < 2; pc++) {
        uint32_t base = smb + pc * STG2;
        int kof = pc * 64;
        #pragma unroll
        for (int i = 0; i < 4; i++) {
            CP_ASYNC16(base + lr[i] * ROWB + ls[i] * 16,
                       Asrc + (size_t)lr[i] * 1024 + kof + ls[i] * 8);
            CP_ASYNC16(base + O_B + lr[i] * ROWB + ls[i] * 16,
                       Bsrc + (size_t)lr[i] * 1024 + kof + ls[i] * 8);
        }
        CP_COMMIT();
    }

    for (int c = 0; c < 16; c++) {
        if (c < 15) CP_WAIT1();     // chunk c done; c+1 may be in flight
        else        CP_WAIT0();
        __syncthreads();            // orders compute of c-1 before prefetch
        if (c + 2 < 16) {
            uint32_t base = smb + ((c + 2) % 3) * STG2;
            int kof = (c + 2) * 64;
            #pragma unroll
            for (int i = 0; i < 4; i++) {
                CP_ASYNC16(base + lr[i] * ROWB + ls[i] * 16,
                           Asrc + (size_t)lr[i] * 1024 + kof + ls[i] * 8);
                CP_ASYNC16(base + O_B + lr[i] * ROWB + ls[i] * 16,
                           Bsrc + (size_t)lr[i] * 1024 + kof + ls[i] * 8);
            }
            CP_COMMIT();
        }
        uint32_t sb = smb + (c % 3) * STG2;
        #pragma unroll
        for (int ks = 0; ks < 4; ks++) {
            uint32_t ah[4][4], bb[4][2];
            #pragma unroll
            for (int mt = 0; mt < 4; mt++) {
                uint32_t ra = sb + (wm * 64 + mt * 16 + a_row) * ROWB
                            + ks * 32 + a_kofs;
                LDSM_X4(ah[mt][0], ah[mt][1], ah[mt][2], ah[mt][3], ra);
            }
            #pragma unroll
            for (int np = 0; np < 2; np++) {
                uint32_t rb = sb + O_B + (wn * 32 + np * 16 + b_rofs) * ROWB
                            + ks * 32 + b_kofs;
                uint32_t r0v, r1v, r2v, r3v;
                LDSM_X4(r0v, r1v, r2v, r3v, rb);
                bb[2 * np][0] = r0v; bb[2 * np][1] = r1v;
                bb[2 * np + 1][0] = r2v; bb[2 * np + 1][1] = r3v;
            }
            #pragma unroll
            for (int mt = 0; mt < 4; mt++)
                #pragma unroll
                for (int nt = 0; nt < 4; nt++)
                    MMA_F16(f.acc[mt][nt], ah[mt], bb[nt]);
        }
    }
}

// ================= fused QKV projection GEMM ================================
__global__ __launch_bounds__(256, 2) void qkv_gemm(
    const __half* __restrict__ e16, const __half* __restrict__ hn16,
    const __half* __restrict__ wk16, const __half* __restrict__ wv16,
    const __half* __restrict__ wq16,
    const float* __restrict__ bk, const float* __restrict__ bv,
    const float* __restrict__ bq,
    __half* __restrict__ k16, __half* __restrict__ v16,
    __half* __restrict__ q16) {
    extern __shared__ char smc[];
    uint32_t smb = smem_u32(smc);
    int tid = threadIdx.x, wid = tid >> 5, lane = tid & 31;
    int bx = blockIdx.x, by = blockIdx.y;
    int wm = wid & 1, wn = wid >> 1;

    const __half* A;
    const __half* B;
    const float* bias;
    __half* C;
    if (by < 256)      { A = e16  + (size_t)by * 131072;        B = wk16; bias = bk; C = k16; }
    else if (by < 512) { A = e16  + (size_t)(by - 256) * 131072; B = wv16; bias = bv; C = v16; }
    else               { A = hn16 + (size_t)(by - 512) * 131072; B = wq16; bias = bq; C = q16; }
    int byo = (by < 256) ? by : (by < 512) ? by - 256 : by - 512;
    const __half* Bsrc = B + (size_t)bx * 131072;

    GemmFrag f;
    gemm_core(A, Bsrc, smc, smb, tid, f);

    int g  = lane >> 2;
    int t2 = (lane & 3) * 2;
    #pragma unroll
    for (int nt = 0; nt < 4; nt++) {
        int col = bx * 128 + wn * 32 + nt * 8 + t2;
        float2 bv2 = *(const float2*)&bias[col];
        #pragma unroll
        for (int mt = 0; mt < 4; mt++) {
            int r = byo * 128 + wm * 64 + mt * 16 + g;
            float v00 = f.acc[mt][nt][0] + bv2.x, v01 = f.acc[mt][nt][1] + bv2.y;
            float v10 = f.acc[mt][nt][2] + bv2.x, v11 = f.acc[mt][nt][3] + bv2.y;
            __half hp0[2] = {__float2half_rn(v00), __float2half_rn(v01)};
            __half hp1[2] = {__float2half_rn(v10), __float2half_rn(v11)};
            *(uint32_t*)&C[(size_t)r * 1024 + col]       = *(uint32_t*)hp0;
            *(uint32_t*)&C[(size_t)(r + 8) * 1024 + col] = *(uint32_t*)hp1;
        }
    }
}

// ================= O projection GEMM with fused shifted residual ============
__global__ __launch_bounds__(256, 2) void o_gemm(
    const __half* __restrict__ ao16, const __half* __restrict__ wo16,
    const float* __restrict__ bo, const float* __restrict__ hres,
    float* __restrict__ out) {
    extern __shared__ char smc[];
    uint32_t smb = smem_u32(smc);
    int tid = threadIdx.x, wid = tid >> 5, lane = tid & 31;
    int bx = blockIdx.x, by = blockIdx.y;
    int wm = wid & 1, wn = wid >> 1;

    GemmFrag f;
    gemm_core(ao16 + (size_t)by * 131072, wo16 + (size_t)bx * 131072,
              smc, smb, tid, f);

    int g  = lane >> 2;
    int t2 = (lane & 3) * 2;
    #pragma unroll
    for (int nt = 0; nt < 4; nt++) {
        int col = bx * 128 + wn * 32 + nt * 8 + t2;
        float2 bv2 = *(const float2*)&bo[col];
        #pragma unroll
        for (int mt = 0; mt < 4; mt++) {
            int r = by * 128 + wm * 64 + mt * 16 + g;
            float v00 = f.acc[mt][nt][0] + bv2.x, v01 = f.acc[mt][nt][1] + bv2.y;
            float v10 = f.acc[mt][nt][2] + bv2.x, v11 = f.acc[mt][nt][3] + bv2.y;
            if ((r & 2047) < LNROWS) {
                size_t o = (size_t)(r + 63) * 1024 + col;
                float2 hv = *(const float2*)&hres[o];
                *(float2*)&out[o] = make_float2(hv.x + v00, hv.y + v01);
            }
            if (((r + 8) & 2047) < LNROWS) {
                size_t o = (size_t)(r + 8 + 63) * 1024 + col;
                float2 hv = *(const float2*)&hres[o];
                *(float2*)&out[o] = make_float2(hv.x + v10, hv.y + v11);
            }
        }
    }
}

// ================= Attention: register softmax, 2 CTAs/SM ===================
#define AROWB 144
#define PROWB 528
#define O_Q   0
#define O_K   9216
#define O_P   0
#define O_VT  46080
#define O_RED 79872
#define ATTN_SMEM 81920

__global__ __launch_bounds__(256, 2) void attn_mma(
    const __half* __restrict__ q16, const __half* __restrict__ k16,
    const __half* __restrict__ v16, __half* __restrict__ ao16) {
    int bid = blockIdx.x;
    int head = bid & 15;
    int bc   = bid >> 4;
    extern __shared__ char smc[];
    uint32_t smb = smem_u32(smc);
    int tid = threadIdx.x, wid = tid >> 5, lane = tid & 31;
    int wm = wid & 1, wn = wid >> 1;

    const size_t qoff = ((size_t)bc * 64)  * DM + head * 64;
    const size_t koff = ((size_t)bc * 256) * DM + head * 64;

    for (int t = tid; t < 512; t += 256) {
        int r = t >> 3, s = t & 7;
        *(uint4*)(smc + O_Q + r * AROWB + s * 16) =
            *(const uint4*)(q16 + qoff + (size_t)r * DM + s * 8);
    }
    for (int t = tid; t < 2048; t += 256) {
        int r = t >> 3, s = t & 7;
        *(uint4*)(smc + O_K + r * AROWB + s * 16) =
            *(const uint4*)(k16 + koff + (size_t)r * DM + s * 8);
    }
    {
        int j = tid;
        __half buf[64];
        #pragma unroll
        for (int s = 0; s < 8; s++)
            *(uint4*)&buf[s * 8] = *(const uint4*)(v16 + koff + (size_t)j * DM + s * 8);
        #pragma unroll
        for (int d = 0; d < 64; d++)
            *(__half*)(smc + O_VT + d * PROWB + j * 2) = buf[d];
    }
    __syncthreads();

    int a_row  = lane & 15;
    int a_kofs = (lane >> 4) * 16;
    int b_rofs = ((lane >> 4) & 1) * 8 + (lane & 7);
    int b_kofs = ((lane >> 3) & 1) * 16;
    int g  = lane >> 2;
    int t2 = (lane & 3) * 2;

    float* redm = (float*)(smc + O_RED);
    float* reds = (float*)(smc + O_RED + 1024);

    {
        float acc[2][8][4];
        #pragma unroll
        for (int mt = 0; mt < 2; mt++)
            #pragma unroll
            for (int nt = 0; nt < 8; nt++)
                #pragma unroll
                for (int i = 0; i < 4; i++) acc[mt][nt][i] = 0.f;
        #pragma unroll
        for (int ks = 0; ks < 4; ks++) {
            uint32_t ah[2][4], bb[8][2];
            #pragma unroll
            for (int mt = 0; mt < 2; mt++) {
                uint32_t ra = smb + O_Q + (wm * 32 + mt * 16 + a_row) * AROWB
                            + ks * 32 + a_kofs;
                LDSM_X4(ah[mt][0], ah[mt][1], ah[mt][2], ah[mt][3], ra);
            }
            #pragma unroll
            for (int np = 0; np < 4; np++) {
                uint32_t rb = smb + O_K + (wn * 64 + np * 16 + b_rofs) * AROWB
                            + ks * 32 + b_kofs;
                uint32_t r0, r1, r2, r3;
                LDSM_X4(r0, r1, r2, r3, rb);
                bb[2 * np][0] = r0; bb[2 * np][1] = r1;
                bb[2 * np + 1][0] = r2; bb[2 * np + 1][1] = r3;
            }
            #pragma unroll
            for (int mt = 0; mt < 2; mt++)
                #pragma unroll
                for (int nt = 0; nt < 8; nt++)
                    MMA_F16(acc[mt][nt], ah[mt], bb[nt]);
        }

        #pragma unroll
        for (int mt = 0; mt < 2; mt++)
            #pragma unroll
            for (int half = 0; half < 2; half++) {
                float m = -1e30f;
                #pragma unroll
                for (int nt = 0; nt < 8; nt++)
                    m = fmaxf(m, fmaxf(acc[mt][nt][half * 2],
                                       acc[mt][nt][half * 2 + 1]));
                m = fmaxf(m, __shfl_xor_sync(0xffffffffu, m, 1));
                m = fmaxf(m, __shfl_xor_sync(0xffffffffu, m, 2));
                if ((lane & 3) == 0)
                    redm[(wm * 32 + mt * 16 + half * 8 + g) * 4 + wn] = m;
            }
        __syncthreads();

        const float scale = 0.125f;
        #pragma unroll
        for (int mt = 0; mt < 2; mt++)
            #pragma unroll
            for (int half = 0; half < 2; half++) {
                int r = wm * 32 + mt * 16 + half * 8 + g;
                float m = fmaxf(fmaxf(redm[r * 4 + 0], redm[r * 4 + 1]),
                                fmaxf(redm[r * 4 + 2], redm[r * 4 + 3]));
                float s = 0.f;
                #pragma unroll
                for (int nt = 0; nt < 8; nt++) {
                    float e0 = __expf((acc[mt][nt][half * 2]     - m) * scale);
                    float e1 = __expf((acc[mt][nt][half * 2 + 1] - m) * scale);
                    acc[mt][nt][half * 2]     = e0;
                    acc[mt][nt][half * 2 + 1] = e1;
                    s += e0 + e1;
                }
                s += __shfl_xor_sync(0xffffffffu, s, 1);
                s += __shfl_xor_sync(0xffffffffu, s, 2);
                if ((lane & 3) == 0) reds[r * 4 + wn] = s;
            }
        __syncthreads();

        #pragma unroll
        for (int mt = 0; mt < 2; mt++)
            #pragma unroll
            for (int half = 0; half < 2; half++) {
                int r = wm * 32 + mt * 16 + half * 8 + g;
                float s = reds[r * 4 + 0] + reds[r * 4 + 1]
                        + reds[r * 4 + 2] + reds[r * 4 + 3];
                float inv = 1.0f / s;
                #pragma unroll
                for (int nt = 0; nt < 8; nt++) {
                    int col = wn * 64 + nt * 8 + t2;
                    __half hp[2] = {
                        __float2half_rn(acc[mt][nt][half * 2]     * inv),
                        __float2half_rn(acc[mt][nt][half * 2 + 1] * inv)};
                    *(uint32_t*)(smc + O_P + r * PROWB + col * 2) = *(uint32_t*)hp;
                }
            }
    }
    __syncthreads();

    {
        float acc[2][2][4];
        #pragma unroll
        for (int mt = 0; mt < 2; mt++)
            #pragma unroll
            for (int nt = 0; nt < 2; nt++)
                #pragma unroll
                for (int i = 0; i < 4; i++) acc[mt][nt][i] = 0.f;
        #pragma unroll 4
        for (int ks = 0; ks < 16; ks++) {
            uint32_t ah[2][4], bb[2][2];
            #pragma unroll
            for (int mt = 0; mt < 2; mt++) {
                uint32_t ra = smb + O_P + (wm * 32 + mt * 16 + a_row) * PROWB
                            + ks * 32 + a_kofs;
                LDSM_X4(ah[mt][0], ah[mt][1], ah[mt][2], ah[mt][3], ra);
            }
            {
                uint32_t rb = smb + O_VT + (wn * 16 + b_rofs) * PROWB
                            + ks * 32 + b_kofs;
                uint32_t r0, r1, r2, r3;
                LDSM_X4(r0, r1, r2, r3, rb);
                bb[0][0] = r0; bb[0][1] = r1; bb[1][0] = r2; bb[1][1] = r3;
            }
            #pragma unroll
            for (int mt = 0; mt < 2; mt++)
                #pragma unroll
                for (int nt = 0; nt < 2; nt++)
                    MMA_F16(acc[mt][nt], ah[mt], bb[nt]);
        }
        #pragma unroll
        for (int mt = 0; mt < 2; mt++)
            #pragma unroll
            for (int nt = 0; nt < 2; nt++) {
                int i0 = wm * 32 + mt * 16 + g;
                int d0 = wn * 16 + nt * 8 + t2;
                size_t base = ((size_t)bc * 64) * DM + head * 64 + d0;
                #pragma unroll
                for (int half = 0; half < 2; half++) {
                    int i = i0 + half * 8;
                    __half hp[2] = {
                        __float2half_rn(acc[mt][nt][half * 2 + 0]),
                        __float2half_rn(acc[mt][nt][half * 2 + 1])};
                    *(uint32_t*)&ao16[base + (size_t)i * DM] = *(uint32_t*)hp;
                }
            }
    }
}

// ================= launch ===================================================
extern "C" void kernel_launch(void* const* d_in, const int* in_sizes, int n_in,
                              void* d_out, int out_size) {
    const float* h     = (const float*)d_in[0];
    const float* e     = (const float*)d_in[1];
    const float* Wq    = (const float*)d_in[2];
    const float* bq    = (const float*)d_in[3];
    const float* Wk    = (const float*)d_in[4];
    const float* bk    = (const float*)d_in[5];
    const float* Wv    = (const float*)d_in[6];
    const float* bv    = (const float*)d_in[7];
    const float* Wo    = (const float*)d_in[8];
    const float* bo    = (const float*)d_in[9];
    const float* gamma = (const float*)d_in[10];
    const float* beta  = (const float*)d_in[11];
    float* out = (float*)d_out;

    __half *hn16, *e16, *ao16, *q16, *k16, *v16, *wq16, *wk16, *wv16, *wo16;
    cudaGetSymbolAddress((void**)&hn16, g_hn16);
    cudaGetSymbolAddress((void**)&e16,  g_e16);
    cudaGetSymbolAddress((void**)&ao16, g_ao16);
    cudaGetSymbolAddress((void**)&q16,  g_q16);
    cudaGetSymbolAddress((void**)&k16,  g_k16);
    cudaGetSymbolAddress((void**)&v16,  g_v16);
    cudaGetSymbolAddress((void**)&wq16, g_wq16);
    cudaGetSymbolAddress((void**)&wk16, g_wk16);
    cudaGetSymbolAddress((void**)&wv16, g_wv16);
    cudaGetSymbolAddress((void**)&wo16, g_wo16);

    cudaFuncSetAttribute(attn_mma, cudaFuncAttributeMaxDynamicSharedMemorySize,
                         ATTN_SMEM);
    cudaFuncSetAttribute(qkv_gemm, cudaFuncAttributeMaxDynamicSharedMemorySize,
                         GSMEM);
    cudaFuncSetAttribute(o_gemm, cudaFuncAttributeMaxDynamicSharedMemorySize,
                         GSMEM);

    // 0: LN + e cvt + 4x weight transpose + headcopy (one launch)
    prep_all<<<45308, 256>>>(h, gamma, beta, e, Wk, Wq, Wv, Wo,
                             hn16, e16, wk16, wq16, wv16, wo16, out);
    // 1: fused Q/K/V projections
    qkv_gemm<<<dim3(8, 576), 256, GSMEM>>>(e16, hn16, wk16, wv16, wq16,
                                           bk, bv, bq, k16, v16, q16);
    // 2: attention
    attn_mma<<<BATCH * CHUNKS * NH, 256, ATTN_SMEM>>>(q16, k16, v16, ao16);
    // 3: O projection + fused shifted-residual epilogue (profiled slot)
    o_gemm<<<dim3(8, 64), 256, GSMEM>>>(ao16, wo16, bo, h, out);
}